// round 3
// baseline (speedup 1.0000x reference)
#include <cuda_runtime.h>
#include <cuda_bf16.h>
#include <cstdint>

#define DIM 128
#define N_NODES_MAX 50000
#define TILE_ROWS 64
#define THREADS 512

// Scratch for the SpMM accumulator (allocation-free rule: __device__ global).
__device__ float g_side[(size_t)N_NODES_MAX * DIM];

// ---------------------------------------------------------------------------
// packed f32x2 helpers (Blackwell: 2x fp32 FMA throughput, PTX-only)
// ---------------------------------------------------------------------------
__device__ __forceinline__ unsigned long long pack2(float a, float b) {
    unsigned long long r;
    asm("mov.b64 %0, {%1, %2};" : "=l"(r) : "f"(a), "f"(b));
    return r;
}
__device__ __forceinline__ void ffma2(unsigned long long& d,
                                      unsigned long long a,
                                      unsigned long long b) {
    asm("fma.rn.f32x2 %0, %1, %2, %3;" : "=l"(d) : "l"(a), "l"(b), "l"(d));
}
__device__ __forceinline__ float2 unpack2(unsigned long long v) {
    float2 r;
    asm("mov.b64 {%0, %1}, %2;" : "=f"(r.x), "=f"(r.y) : "l"(v));
    return r;
}

// ---------------------------------------------------------------------------
// Kernel: COO scatter:  side[rows[e], :] += vals[e] * ego[cols[e], :]
// One warp per edge; each lane handles one float4 (32 lanes * 4 = 128).
// Vector reduction (red.global.add.v4.f32) to cut L2 atomic op count 4x.
// ---------------------------------------------------------------------------
__global__ void scatter_kernel(const float* __restrict__ ego,
                               const float* __restrict__ vals,
                               const int*   __restrict__ rows,
                               const int*   __restrict__ cols,
                               int E) {
    int gw = (blockIdx.x * blockDim.x + threadIdx.x) >> 5;
    if (gw >= E) return;
    int lane = threadIdx.x & 31;

    int   c = __ldg(&cols[gw]);
    int   r = __ldg(&rows[gw]);
    float v = __ldg(&vals[gw]);

    float4 x = reinterpret_cast<const float4*>(ego + (size_t)c * DIM)[lane];
    float* dst = g_side + (size_t)r * DIM + lane * 4;
    asm volatile("red.global.add.v4.f32 [%0], {%1,%2,%3,%4};"
                 :: "l"(dst), "f"(v * x.x), "f"(v * x.y), "f"(v * x.z), "f"(v * x.w)
                 : "memory");
}

// ---------------------------------------------------------------------------
// Kernel: fused dense part, f32x2 packed FMA inner loop, 512 threads
//   side_r = bf16_round(side)
//   out = lrelu((ego+side_r) @ W1^T + b1) + lrelu((ego*side_r) @ W2^T + b2)
// 16 warps/CTA -> 4 warps/SMSP to hide LDS + pack latency chains.
// Each warp: 4 rows x 128 cols (4 cols/lane).
// ---------------------------------------------------------------------------
#define WT_STRIDE 132
#define SMEM_FLOATS (2 * DIM * WT_STRIDE + 2 * TILE_ROWS * DIM)
#define SMEM_BYTES  (SMEM_FLOATS * 4)

__global__ void __launch_bounds__(THREADS, 1)
dense_kernel(const float* __restrict__ ego,
             const float* __restrict__ W1, const float* __restrict__ b1,
             const float* __restrict__ W2, const float* __restrict__ b2,
             float* __restrict__ out, int n) {
    extern __shared__ float smem[];
    float* Wt1 = smem;                       // [128][132]  Wt1[k][o] = W1[o][k]
    float* Wt2 = Wt1 + DIM * WT_STRIDE;      // [128][132]
    float* s_t = Wt2 + DIM * WT_STRIDE;      // [64][128]
    float* p_t = s_t + TILE_ROWS * DIM;      // [64][128]

    int tid  = threadIdx.x;
    int warp = tid >> 5;                     // 0..15
    int lane = tid & 31;

    // Stage transposed weights (one-time; W is L2-resident).
    for (int i = tid; i < DIM * DIM; i += THREADS) {
        int o = i & (DIM - 1);
        int k = i >> 7;
        Wt1[k * WT_STRIDE + o] = __ldg(&W1[o * DIM + k]);
        Wt2[k * WT_STRIDE + o] = __ldg(&W2[o * DIM + k]);
    }
    float4 b1v = reinterpret_cast<const float4*>(b1)[lane];
    float4 b2v = reinterpret_cast<const float4*>(b2)[lane];
    __syncthreads();

    int numTiles = (n + TILE_ROWS - 1) / TILE_ROWS;
    const float4* ego4  = reinterpret_cast<const float4*>(ego);
    const float4* side4 = reinterpret_cast<const float4*>(g_side);
    float4* out4 = reinterpret_cast<float4*>(out);

    for (int tile = blockIdx.x; tile < numTiles; tile += gridDim.x) {
        int row0 = tile * TILE_ROWS;

        // ---- fill s/p tile (64 rows * 32 float4 = 2048 items) ----
        for (int i = tid; i < TILE_ROWS * (DIM / 4); i += THREADS) {
            int r   = i >> 5;
            int c   = i & 31;
            int row = row0 + r;
            float4 e = make_float4(0.f, 0.f, 0.f, 0.f);
            float4 d = e;
            if (row < n) {
                e = ego4[(size_t)row * 32 + c];
                d = side4[(size_t)row * 32 + c];
            }
            // bf16 round-trip (matches reference astype(bf16).astype(f32))
            d.x = __bfloat162float(__float2bfloat16(d.x));
            d.y = __bfloat162float(__float2bfloat16(d.y));
            d.z = __bfloat162float(__float2bfloat16(d.z));
            d.w = __bfloat162float(__float2bfloat16(d.w));
            float4 s = make_float4(e.x + d.x, e.y + d.y, e.z + d.z, e.w + d.w);
            float4 p = make_float4(e.x * d.x, e.y * d.y, e.z * d.z, e.w * d.w);
            reinterpret_cast<float4*>(s_t)[i] = s;
            reinterpret_cast<float4*>(p_t)[i] = p;
        }
        __syncthreads();

        // ---- compute: warp handles rows [warp*4, warp*4+4) of the tile ----
        unsigned long long acc1[4][2];
        unsigned long long acc2[4][2];
        #pragma unroll
        for (int r = 0; r < 4; r++) {
            acc1[r][0] = 0ull; acc1[r][1] = 0ull;
            acc2[r][0] = 0ull; acc2[r][1] = 0ull;
        }

        const float* srow = s_t + (warp * 4) * DIM;
        const float* prow = p_t + (warp * 4) * DIM;

        for (int k0 = 0; k0 < DIM; k0 += 4) {
            ulonglong2 w1v[4], w2v[4];
            #pragma unroll
            for (int kk = 0; kk < 4; kk++) {
                w1v[kk] = *reinterpret_cast<const ulonglong2*>(
                              Wt1 + (k0 + kk) * WT_STRIDE + lane * 4);
                w2v[kk] = *reinterpret_cast<const ulonglong2*>(
                              Wt2 + (k0 + kk) * WT_STRIDE + lane * 4);
            }
            #pragma unroll
            for (int r = 0; r < 4; r++) {
                float4 sv = *reinterpret_cast<const float4*>(srow + r * DIM + k0);
                float4 pv = *reinterpret_cast<const float4*>(prow + r * DIM + k0);
                unsigned long long sb, pb;

                sb = pack2(sv.x, sv.x);
                ffma2(acc1[r][0], sb, w1v[0].x); ffma2(acc1[r][1], sb, w1v[0].y);
                pb = pack2(pv.x, pv.x);
                ffma2(acc2[r][0], pb, w2v[0].x); ffma2(acc2[r][1], pb, w2v[0].y);

                sb = pack2(sv.y, sv.y);
                ffma2(acc1[r][0], sb, w1v[1].x); ffma2(acc1[r][1], sb, w1v[1].y);
                pb = pack2(pv.y, pv.y);
                ffma2(acc2[r][0], pb, w2v[1].x); ffma2(acc2[r][1], pb, w2v[1].y);

                sb = pack2(sv.z, sv.z);
                ffma2(acc1[r][0], sb, w1v[2].x); ffma2(acc1[r][1], sb, w1v[2].y);
                pb = pack2(pv.z, pv.z);
                ffma2(acc2[r][0], pb, w2v[2].x); ffma2(acc2[r][1], pb, w2v[2].y);

                sb = pack2(sv.w, sv.w);
                ffma2(acc1[r][0], sb, w1v[3].x); ffma2(acc1[r][1], sb, w1v[3].y);
                pb = pack2(pv.w, pv.w);
                ffma2(acc2[r][0], pb, w2v[3].x); ffma2(acc2[r][1], pb, w2v[3].y);
            }
        }

        // ---- epilogue: bias + leaky_relu(0.01) + sum, store ----
        #pragma unroll
        for (int r = 0; r < 4; r++) {
            int row = row0 + warp * 4 + r;
            if (row < n) {
                float2 a1lo = unpack2(acc1[r][0]);
                float2 a1hi = unpack2(acc1[r][1]);
                float2 a2lo = unpack2(acc2[r][0]);
                float2 a2hi = unpack2(acc2[r][1]);
                float4 o;
                float v1, v2;
                v1 = a1lo.x + b1v.x; v1 = v1 > 0.f ? v1 : 0.01f * v1;
                v2 = a2lo.x + b2v.x; v2 = v2 > 0.f ? v2 : 0.01f * v2;
                o.x = v1 + v2;
                v1 = a1lo.y + b1v.y; v1 = v1 > 0.f ? v1 : 0.01f * v1;
                v2 = a2lo.y + b2v.y; v2 = v2 > 0.f ? v2 : 0.01f * v2;
                o.y = v1 + v2;
                v1 = a1hi.x + b1v.z; v1 = v1 > 0.f ? v1 : 0.01f * v1;
                v2 = a2hi.x + b2v.z; v2 = v2 > 0.f ? v2 : 0.01f * v2;
                o.z = v1 + v2;
                v1 = a1hi.y + b1v.w; v1 = v1 > 0.f ? v1 : 0.01f * v1;
                v2 = a2hi.y + b2v.w; v2 = v2 > 0.f ? v2 : 0.01f * v2;
                o.w = v1 + v2;
                out4[(size_t)row * 32 + lane] = o;
            }
        }
        __syncthreads();
    }
}

// ---------------------------------------------------------------------------
extern "C" void kernel_launch(void* const* d_in, const int* in_sizes, int n_in,
                              void* d_out, int out_size) {
    const float* ego  = (const float*)d_in[0];
    const float* vals = (const float*)d_in[1];
    const float* W1   = (const float*)d_in[2];
    const float* b1   = (const float*)d_in[3];
    const float* W2   = (const float*)d_in[4];
    const float* b2   = (const float*)d_in[5];
    const int*   rows = (const int*)d_in[6];
    const int*   cols = (const int*)d_in[7];
    float*       out  = (float*)d_out;

    int n = in_sizes[0] / DIM;   // 50000
    int E = in_sizes[1];         // 640000

    cudaFuncSetAttribute(dense_kernel,
                         cudaFuncAttributeMaxDynamicSharedMemorySize, SMEM_BYTES);

    // 1) zero scratch (async memset: graph-capturable, no alloc)
    void* side_ptr = nullptr;
    cudaGetSymbolAddress(&side_ptr, g_side);
    cudaMemsetAsync(side_ptr, 0, (size_t)n * DIM * sizeof(float));

    // 2) edge scatter (one warp per edge, 8 warps/block)
    int blocks = (E + 7) / 8;
    scatter_kernel<<<blocks, 256>>>(ego, vals, rows, cols, E);

    // 3) fused dense
    dense_kernel<<<148, THREADS, SMEM_BYTES>>>(ego, W1, b1, W2, b2, out, n);
}

// round 4
// speedup vs baseline: 1.4179x; 1.4179x over previous
#include <cuda_runtime.h>
#include <cuda_bf16.h>
#include <cstdint>

#define DIM 128
#define N_NODES_MAX 50000
#define TILE_M 64
#define THREADS 256
#define SA 136   // bf16-element row stride (272B = odd*16B -> ldmatrix conflict-free)

// Scratch for the SpMM accumulator (allocation-free rule: __device__ global).
__device__ float g_side[(size_t)N_NODES_MAX * DIM];

// ---- smem layout (bf16 elements) ----
#define OFF_SH  0
#define OFF_SL  (OFF_SH  + TILE_M * SA)
#define OFF_PH  (OFF_SL  + TILE_M * SA)
#define OFF_PL  (OFF_PH  + TILE_M * SA)
#define OFF_W1H (OFF_PL  + TILE_M * SA)
#define OFF_W1L (OFF_W1H + DIM * SA)
#define OFF_W2H (OFF_W1L + DIM * SA)
#define OFF_W2L (OFF_W2H + DIM * SA)
#define SMEM_ELEMS (OFF_W2L + DIM * SA)
#define SMEM_BYTES (SMEM_ELEMS * 2)

// ---------------------------------------------------------------------------
// Kernel: COO scatter:  side[rows[e], :] += vals[e] * ego[cols[e], :]
// ---------------------------------------------------------------------------
__global__ void scatter_kernel(const float* __restrict__ ego,
                               const float* __restrict__ vals,
                               const int*   __restrict__ rows,
                               const int*   __restrict__ cols,
                               int E) {
    int gw = (blockIdx.x * blockDim.x + threadIdx.x) >> 5;
    if (gw >= E) return;
    int lane = threadIdx.x & 31;

    int   c = __ldg(&cols[gw]);
    int   r = __ldg(&rows[gw]);
    float v = __ldg(&vals[gw]);

    float4 x = reinterpret_cast<const float4*>(ego + (size_t)c * DIM)[lane];
    float* dst = g_side + (size_t)r * DIM + lane * 4;
    asm volatile("red.global.add.v4.f32 [%0], {%1,%2,%3,%4};"
                 :: "l"(dst), "f"(v * x.x), "f"(v * x.y), "f"(v * x.z), "f"(v * x.w)
                 : "memory");
}

// ---------------------------------------------------------------------------
// mma.sync / ldmatrix helpers
// ---------------------------------------------------------------------------
__device__ __forceinline__ void ldsm_x4(uint32_t* r, uint32_t addr) {
    asm volatile("ldmatrix.sync.aligned.m8n8.x4.shared.b16 {%0,%1,%2,%3}, [%4];"
                 : "=r"(r[0]), "=r"(r[1]), "=r"(r[2]), "=r"(r[3]) : "r"(addr));
}
__device__ __forceinline__ void mma_bf16(float* d, const uint32_t* a,
                                         uint32_t b0, uint32_t b1) {
    asm volatile("mma.sync.aligned.m16n8k16.row.col.f32.bf16.bf16.f32 "
                 "{%0,%1,%2,%3}, {%4,%5,%6,%7}, {%8,%9}, {%0,%1,%2,%3};"
                 : "+f"(d[0]), "+f"(d[1]), "+f"(d[2]), "+f"(d[3])
                 : "r"(a[0]), "r"(a[1]), "r"(a[2]), "r"(a[3]), "r"(b0), "r"(b1));
}
__device__ __forceinline__ float lrelu(float v) { return v > 0.f ? v : 0.01f * v; }

// ---------------------------------------------------------------------------
// Dense kernel (tensor cores, 3-term bf16 split for fp32 accuracy):
//   side_r = bf16_round(side); s = ego + side_r; p = ego * side_r
//   out = lrelu(s @ W1^T + b1) + lrelu(p @ W2^T + b2)
// ---------------------------------------------------------------------------
__global__ void __launch_bounds__(THREADS, 1)
dense_kernel(const float* __restrict__ ego,
             const float* __restrict__ W1, const float* __restrict__ b1,
             const float* __restrict__ W2, const float* __restrict__ b2,
             float* __restrict__ out, int n) {
    extern __shared__ __nv_bfloat16 sm[];
    uint32_t sbase = (uint32_t)__cvta_generic_to_shared(sm);

    int tid  = threadIdx.x;
    int warp = tid >> 5;
    int lane = tid & 31;
    int warp_m = (warp >> 2) * 32;   // 0 or 32
    int warp_n = (warp & 3) * 32;    // 0,32,64,96

    // ---- one-time: split weights to bf16 hi/lo in smem ----
    for (int i = tid; i < DIM * DIM; i += THREADS) {
        int o = i >> 7, k = i & (DIM - 1);
        float w1 = __ldg(&W1[i]);
        float w2 = __ldg(&W2[i]);
        __nv_bfloat16 h1 = __float2bfloat16_rn(w1);
        __nv_bfloat16 h2 = __float2bfloat16_rn(w2);
        sm[OFF_W1H + o * SA + k] = h1;
        sm[OFF_W1L + o * SA + k] = __float2bfloat16_rn(w1 - __bfloat162float(h1));
        sm[OFF_W2H + o * SA + k] = h2;
        sm[OFF_W2L + o * SA + k] = __float2bfloat16_rn(w2 - __bfloat162float(h2));
    }

    // ---- per-thread bias (cols this thread owns in the output frags) ----
    int col_base = warp_n + (lane & 3) * 2;
    float2 b1v[4], b2v[4];
    #pragma unroll
    for (int nb = 0; nb < 4; nb++) {
        b1v[nb] = *reinterpret_cast<const float2*>(b1 + col_base + nb * 8);
        b2v[nb] = *reinterpret_cast<const float2*>(b2 + col_base + nb * 8);
    }
    __syncthreads();

    // ---- per-thread ldmatrix byte offsets ----
    int lrow = lane & 15;
    int lcol = (lane >> 4) * 8;
    uint32_t a_byte[2], b_byte[2];
    #pragma unroll
    for (int mb = 0; mb < 2; mb++)
        a_byte[mb] = ((warp_m + mb * 16 + lrow) * SA + lcol) * 2;
    #pragma unroll
    for (int np = 0; np < 2; np++)
        b_byte[np] = ((warp_n + np * 16 + lrow) * SA + lcol) * 2;

    int numTiles = (n + TILE_M - 1) / TILE_M;
    const float4* ego4  = reinterpret_cast<const float4*>(ego);
    const float4* side4 = reinterpret_cast<const float4*>(g_side);

    for (int tile = blockIdx.x; tile < numTiles; tile += gridDim.x) {
        int row0 = tile * TILE_M;

        // ---- prologue: build split A-tiles (s_hi/s_lo/p_hi/p_lo) ----
        for (int i = tid; i < TILE_M * (DIM / 4); i += THREADS) {
            int r  = i >> 5;
            int c4 = i & 31;
            int row = row0 + r;
            float4 e = make_float4(0.f, 0.f, 0.f, 0.f);
            float4 d = e;
            if (row < n) {
                e = ego4[(size_t)row * 32 + c4];
                d = side4[(size_t)row * 32 + c4];
            }
            // bf16 round-trip of side (matches reference)
            d.x = __bfloat162float(__float2bfloat16(d.x));
            d.y = __bfloat162float(__float2bfloat16(d.y));
            d.z = __bfloat162float(__float2bfloat16(d.z));
            d.w = __bfloat162float(__float2bfloat16(d.w));
            float4 s = make_float4(e.x + d.x, e.y + d.y, e.z + d.z, e.w + d.w);
            float4 p = make_float4(e.x * d.x, e.y * d.y, e.z * d.z, e.w * d.w);

            int off = r * SA + c4 * 4;
            __nv_bfloat162* sh2 = reinterpret_cast<__nv_bfloat162*>(sm + OFF_SH + off);
            __nv_bfloat162* sl2 = reinterpret_cast<__nv_bfloat162*>(sm + OFF_SL + off);
            __nv_bfloat162* ph2 = reinterpret_cast<__nv_bfloat162*>(sm + OFF_PH + off);
            __nv_bfloat162* pl2 = reinterpret_cast<__nv_bfloat162*>(sm + OFF_PL + off);

            __nv_bfloat16 hx, hy, hz, hw;
            hx = __float2bfloat16_rn(s.x); hy = __float2bfloat16_rn(s.y);
            hz = __float2bfloat16_rn(s.z); hw = __float2bfloat16_rn(s.w);
            sh2[0] = __nv_bfloat162(hx, hy);
            sh2[1] = __nv_bfloat162(hz, hw);
            sl2[0] = __nv_bfloat162(__float2bfloat16_rn(s.x - __bfloat162float(hx)),
                                    __float2bfloat16_rn(s.y - __bfloat162float(hy)));
            sl2[1] = __nv_bfloat162(__float2bfloat16_rn(s.z - __bfloat162float(hz)),
                                    __float2bfloat16_rn(s.w - __bfloat162float(hw)));
            hx = __float2bfloat16_rn(p.x); hy = __float2bfloat16_rn(p.y);
            hz = __float2bfloat16_rn(p.z); hw = __float2bfloat16_rn(p.w);
            ph2[0] = __nv_bfloat162(hx, hy);
            ph2[1] = __nv_bfloat162(hz, hw);
            pl2[0] = __nv_bfloat162(__float2bfloat16_rn(p.x - __bfloat162float(hx)),
                                    __float2bfloat16_rn(p.y - __bfloat162float(hy)));
            pl2[1] = __nv_bfloat162(__float2bfloat16_rn(p.z - __bfloat162float(hz)),
                                    __float2bfloat16_rn(p.w - __bfloat162float(hw)));
        }
        __syncthreads();

        // ---- main loop: 8 k-steps of 16 ----
        float d1[2][4][4];
        float d2[2][4][4];
        #pragma unroll
        for (int mb = 0; mb < 2; mb++)
            #pragma unroll
            for (int nb = 0; nb < 4; nb++)
                #pragma unroll
                for (int j = 0; j < 4; j++) { d1[mb][nb][j] = 0.f; d2[mb][nb][j] = 0.f; }

        #pragma unroll
        for (int ks = 0; ks < 8; ks++) {
            uint32_t k2 = ks * 32;   // 16 bf16 = 32 bytes

            uint32_t sh[2][4], sl[2][4], ph[2][4], pl[2][4];
            #pragma unroll
            for (int mb = 0; mb < 2; mb++) {
                ldsm_x4(sh[mb], sbase + OFF_SH * 2 + a_byte[mb] + k2);
                ldsm_x4(sl[mb], sbase + OFF_SL * 2 + a_byte[mb] + k2);
                ldsm_x4(ph[mb], sbase + OFF_PH * 2 + a_byte[mb] + k2);
                ldsm_x4(pl[mb], sbase + OFF_PL * 2 + a_byte[mb] + k2);
            }
            uint32_t w1h[2][4], w1l[2][4], w2h[2][4], w2l[2][4];
            #pragma unroll
            for (int np = 0; np < 2; np++) {
                ldsm_x4(w1h[np], sbase + OFF_W1H * 2 + b_byte[np] + k2);
                ldsm_x4(w1l[np], sbase + OFF_W1L * 2 + b_byte[np] + k2);
                ldsm_x4(w2h[np], sbase + OFF_W2H * 2 + b_byte[np] + k2);
                ldsm_x4(w2l[np], sbase + OFF_W2L * 2 + b_byte[np] + k2);
            }

            #pragma unroll
            for (int mb = 0; mb < 2; mb++) {
                #pragma unroll
                for (int np = 0; np < 2; np++) {
                    #pragma unroll
                    for (int j = 0; j < 2; j++) {
                        int nb = np * 2 + j;
                        // s path: hi*Whi + lo*Whi + hi*Wlo
                        mma_bf16(d1[mb][nb], sh[mb], w1h[np][j], w1h[np][j + 2]);
                        mma_bf16(d1[mb][nb], sl[mb], w1h[np][j], w1h[np][j + 2]);
                        mma_bf16(d1[mb][nb], sh[mb], w1l[np][j], w1l[np][j + 2]);
                        // p path
                        mma_bf16(d2[mb][nb], ph[mb], w2h[np][j], w2h[np][j + 2]);
                        mma_bf16(d2[mb][nb], pl[mb], w2h[np][j], w2h[np][j + 2]);
                        mma_bf16(d2[mb][nb], ph[mb], w2l[np][j], w2l[np][j + 2]);
                    }
                }
            }
        }
        __syncthreads();   // all warps done reading A-tiles before next prologue

        // ---- epilogue: bias + leaky_relu + sum, store fp32 ----
        #pragma unroll
        for (int mb = 0; mb < 2; mb++) {
            int r_lo = row0 + warp_m + mb * 16 + (lane >> 2);
            int r_hi = r_lo + 8;
            #pragma unroll
            for (int nb = 0; nb < 4; nb++) {
                int col = col_base + nb * 8;
                if (r_lo < n) {
                    float2 o;
                    o.x = lrelu(d1[mb][nb][0] + b1v[nb].x) + lrelu(d2[mb][nb][0] + b2v[nb].x);
                    o.y = lrelu(d1[mb][nb][1] + b1v[nb].y) + lrelu(d2[mb][nb][1] + b2v[nb].y);
                    *reinterpret_cast<float2*>(out + (size_t)r_lo * DIM + col) = o;
                }
                if (r_hi < n) {
                    float2 o;
                    o.x = lrelu(d1[mb][nb][2] + b1v[nb].x) + lrelu(d2[mb][nb][2] + b2v[nb].x);
                    o.y = lrelu(d1[mb][nb][3] + b1v[nb].y) + lrelu(d2[mb][nb][3] + b2v[nb].y);
                    *reinterpret_cast<float2*>(out + (size_t)r_hi * DIM + col) = o;
                }
            }
        }
    }
}

// ---------------------------------------------------------------------------
extern "C" void kernel_launch(void* const* d_in, const int* in_sizes, int n_in,
                              void* d_out, int out_size) {
    const float* ego  = (const float*)d_in[0];
    const float* vals = (const float*)d_in[1];
    const float* W1   = (const float*)d_in[2];
    const float* b1   = (const float*)d_in[3];
    const float* W2   = (const float*)d_in[4];
    const float* b2   = (const float*)d_in[5];
    const int*   rows = (const int*)d_in[6];
    const int*   cols = (const int*)d_in[7];
    float*       out  = (float*)d_out;

    int n = in_sizes[0] / DIM;   // 50000
    int E = in_sizes[1];         // 640000

    cudaFuncSetAttribute(dense_kernel,
                         cudaFuncAttributeMaxDynamicSharedMemorySize, SMEM_BYTES);

    // 1) zero scratch (async memset: graph-capturable, no alloc)
    void* side_ptr = nullptr;
    cudaGetSymbolAddress(&side_ptr, g_side);
    cudaMemsetAsync(side_ptr, 0, (size_t)n * DIM * sizeof(float));

    // 2) edge scatter (one warp per edge, 8 warps/block)
    int blocks = (E + 7) / 8;
    scatter_kernel<<<blocks, 256>>>(ego, vals, rows, cols, E);

    // 3) fused dense (tensor cores)
    dense_kernel<<<148, THREADS, SMEM_BYTES>>>(ego, W1, b1, W2, b2, out, n);
}

// round 7
// speedup vs baseline: 1.5061x; 1.0622x over previous
#include <cuda_runtime.h>
#include <cuda_bf16.h>
#include <cstdint>

#define DIM 128
#define N_NODES_MAX 50000
#define TILE_M 64
#define THREADS 512
#define SA 136   // bf16-element row stride (272B = odd*16B -> ldmatrix conflict-free)

// Scratch for the SpMM accumulator (allocation-free rule: __device__ global).
__device__ float g_side[(size_t)N_NODES_MAX * DIM];

// ---- smem layout for dense kernel (bf16 elements) ----
#define OFF_SH  0
#define OFF_SL  (OFF_SH  + TILE_M * SA)
#define OFF_PH  (OFF_SL  + TILE_M * SA)
#define OFF_PL  (OFF_PH  + TILE_M * SA)
#define OFF_W1H (OFF_PL  + TILE_M * SA)
#define OFF_W1L (OFF_W1H + DIM * SA)
#define OFF_W2H (OFF_W1L + DIM * SA)
#define OFF_W2L (OFF_W2H + DIM * SA)
#define SMEM_ELEMS (OFF_W2L + DIM * SA)
#define SMEM_BYTES (SMEM_ELEMS * 2)

// ---------------------------------------------------------------------------
// Kernel: COO scatter:  side[rows[e], :] += vals[e] * ego[cols[e], :]
// One warp per edge; vector reduction cuts L2 atomic op count 4x.
// ---------------------------------------------------------------------------
__global__ void scatter_kernel(const float* __restrict__ ego,
                               const float* __restrict__ vals,
                               const int*   __restrict__ rows,
                               const int*   __restrict__ cols,
                               int E) {
    int gw = (blockIdx.x * blockDim.x + threadIdx.x) >> 5;
    if (gw >= E) return;
    int lane = threadIdx.x & 31;

    int   c = __ldg(&cols[gw]);
    int   r = __ldg(&rows[gw]);
    float v = __ldg(&vals[gw]);

    float4 x = reinterpret_cast<const float4*>(ego + (size_t)c * DIM)[lane];
    float* dst = g_side + (size_t)r * DIM + lane * 4;
    asm volatile("red.global.add.v4.f32 [%0], {%1,%2,%3,%4};"
                 :: "l"(dst), "f"(v * x.x), "f"(v * x.y), "f"(v * x.z), "f"(v * x.w)
                 : "memory");
}

// ---------------------------------------------------------------------------
// mma.sync / ldmatrix helpers
// ---------------------------------------------------------------------------
__device__ __forceinline__ void ldsm_x4(uint32_t* r, uint32_t addr) {
    asm volatile("ldmatrix.sync.aligned.m8n8.x4.shared.b16 {%0,%1,%2,%3}, [%4];"
                 : "=r"(r[0]), "=r"(r[1]), "=r"(r[2]), "=r"(r[3]) : "r"(addr));
}
__device__ __forceinline__ void mma_bf16(float* d, const uint32_t* a,
                                         uint32_t b0, uint32_t b1) {
    asm volatile("mma.sync.aligned.m16n8k16.row.col.f32.bf16.bf16.f32 "
                 "{%0,%1,%2,%3}, {%4,%5,%6,%7}, {%8,%9}, {%0,%1,%2,%3};"
                 : "+f"(d[0]), "+f"(d[1]), "+f"(d[2]), "+f"(d[3])
                 : "r"(a[0]), "r"(a[1]), "r"(a[2]), "r"(a[3]), "r"(b0), "r"(b1));
}
__device__ __forceinline__ float lrelu(float v) { return v > 0.f ? v : 0.01f * v; }

// ---------------------------------------------------------------------------
// Dense kernel (tensor cores, 3-term bf16 split; 16 warps, warp tile 16x32):
//   side_r = bf16_round(side); s = ego + side_r; p = ego * side_r
//   out = lrelu(s @ W1^T + b1) + lrelu(p @ W2^T + b2)
// ---------------------------------------------------------------------------
__global__ void __launch_bounds__(THREADS, 1)
dense_kernel(const float* __restrict__ ego,
             const float* __restrict__ W1, const float* __restrict__ b1,
             const float* __restrict__ W2, const float* __restrict__ b2,
             float* __restrict__ out, int n) {
    extern __shared__ __nv_bfloat16 sm[];
    uint32_t sbase = (uint32_t)__cvta_generic_to_shared(sm);

    int tid  = threadIdx.x;
    int warp = tid >> 5;                 // 0..15
    int lane = tid & 31;
    int warp_m = (warp >> 2) * 16;       // 0,16,32,48
    int warp_n = (warp & 3) * 32;        // 0,32,64,96

    // ---- one-time: split weights to bf16 hi/lo in smem ----
    for (int i = tid; i < DIM * DIM; i += THREADS) {
        int o = i >> 7, k = i & (DIM - 1);
        float w1 = __ldg(&W1[i]);
        float w2 = __ldg(&W2[i]);
        __nv_bfloat16 h1 = __float2bfloat16_rn(w1);
        __nv_bfloat16 h2 = __float2bfloat16_rn(w2);
        sm[OFF_W1H + o * SA + k] = h1;
        sm[OFF_W1L + o * SA + k] = __float2bfloat16_rn(w1 - __bfloat162float(h1));
        sm[OFF_W2H + o * SA + k] = h2;
        sm[OFF_W2L + o * SA + k] = __float2bfloat16_rn(w2 - __bfloat162float(h2));
    }

    // ---- per-thread bias ----
    int col_base = warp_n + (lane & 3) * 2;
    float2 b1v[4], b2v[4];
    #pragma unroll
    for (int nb = 0; nb < 4; nb++) {
        b1v[nb] = *reinterpret_cast<const float2*>(b1 + col_base + nb * 8);
        b2v[nb] = *reinterpret_cast<const float2*>(b2 + col_base + nb * 8);
    }
    __syncthreads();

    // ---- per-thread ldmatrix byte offsets ----
    int lrow = lane & 15;
    int lcol = (lane >> 4) * 8;
    uint32_t a_byte = ((warp_m + lrow) * SA + lcol) * 2;
    uint32_t b_byte[2];
    #pragma unroll
    for (int np = 0; np < 2; np++)
        b_byte[np] = ((warp_n + np * 16 + lrow) * SA + lcol) * 2;

    int numTiles = (n + TILE_M - 1) / TILE_M;
    const float4* ego4  = reinterpret_cast<const float4*>(ego);
    const float4* side4 = reinterpret_cast<const float4*>(g_side);

    for (int tile = blockIdx.x; tile < numTiles; tile += gridDim.x) {
        int row0 = tile * TILE_M;

        // ---- prologue: build split A-tiles (s_hi/s_lo/p_hi/p_lo) ----
        for (int i = tid; i < TILE_M * (DIM / 4); i += THREADS) {
            int r  = i >> 5;
            int c4 = i & 31;
            int row = row0 + r;
            float4 e = make_float4(0.f, 0.f, 0.f, 0.f);
            float4 d = e;
            if (row < n) {
                e = ego4[(size_t)row * 32 + c4];
                d = side4[(size_t)row * 32 + c4];
            }
            // bf16 round-trip of side (matches reference)
            d.x = __bfloat162float(__float2bfloat16(d.x));
            d.y = __bfloat162float(__float2bfloat16(d.y));
            d.z = __bfloat162float(__float2bfloat16(d.z));
            d.w = __bfloat162float(__float2bfloat16(d.w));
            float4 s = make_float4(e.x + d.x, e.y + d.y, e.z + d.z, e.w + d.w);
            float4 p = make_float4(e.x * d.x, e.y * d.y, e.z * d.z, e.w * d.w);

            int off = r * SA + c4 * 4;
            __nv_bfloat162* sh2 = reinterpret_cast<__nv_bfloat162*>(sm + OFF_SH + off);
            __nv_bfloat162* sl2 = reinterpret_cast<__nv_bfloat162*>(sm + OFF_SL + off);
            __nv_bfloat162* ph2 = reinterpret_cast<__nv_bfloat162*>(sm + OFF_PH + off);
            __nv_bfloat162* pl2 = reinterpret_cast<__nv_bfloat162*>(sm + OFF_PL + off);

            __nv_bfloat16 hx, hy, hz, hw;
            hx = __float2bfloat16_rn(s.x); hy = __float2bfloat16_rn(s.y);
            hz = __float2bfloat16_rn(s.z); hw = __float2bfloat16_rn(s.w);
            sh2[0] = __nv_bfloat162(hx, hy);
            sh2[1] = __nv_bfloat162(hz, hw);
            sl2[0] = __nv_bfloat162(__float2bfloat16_rn(s.x - __bfloat162float(hx)),
                                    __float2bfloat16_rn(s.y - __bfloat162float(hy)));
            sl2[1] = __nv_bfloat162(__float2bfloat16_rn(s.z - __bfloat162float(hz)),
                                    __float2bfloat16_rn(s.w - __bfloat162float(hw)));
            hx = __float2bfloat16_rn(p.x); hy = __float2bfloat16_rn(p.y);
            hz = __float2bfloat16_rn(p.z); hw = __float2bfloat16_rn(p.w);
            ph2[0] = __nv_bfloat162(hx, hy);
            ph2[1] = __nv_bfloat162(hz, hw);
            pl2[0] = __nv_bfloat162(__float2bfloat16_rn(p.x - __bfloat162float(hx)),
                                    __float2bfloat16_rn(p.y - __bfloat162float(hy)));
            pl2[1] = __nv_bfloat162(__float2bfloat16_rn(p.z - __bfloat162float(hz)),
                                    __float2bfloat16_rn(p.w - __bfloat162float(hw)));
        }
        __syncthreads();

        // ---- main loop: 8 k-steps of 16 ----
        float d1[4][4];
        float d2[4][4];
        #pragma unroll
        for (int nb = 0; nb < 4; nb++)
            #pragma unroll
            for (int j = 0; j < 4; j++) { d1[nb][j] = 0.f; d2[nb][j] = 0.f; }

        #pragma unroll
        for (int ks = 0; ks < 8; ks++) {
            uint32_t k2 = ks * 32;   // 16 bf16 = 32 bytes

            uint32_t sh[4], sl[4], ph[4], pl[4];
            ldsm_x4(sh, sbase + OFF_SH * 2 + a_byte + k2);
            ldsm_x4(sl, sbase + OFF_SL * 2 + a_byte + k2);
            ldsm_x4(ph, sbase + OFF_PH * 2 + a_byte + k2);
            ldsm_x4(pl, sbase + OFF_PL * 2 + a_byte + k2);

            uint32_t w1h[2][4], w1l[2][4], w2h[2][4], w2l[2][4];
            #pragma unroll
            for (int np = 0; np < 2; np++) {
                ldsm_x4(w1h[np], sbase + OFF_W1H * 2 + b_byte[np] + k2);
                ldsm_x4(w1l[np], sbase + OFF_W1L * 2 + b_byte[np] + k2);
                ldsm_x4(w2h[np], sbase + OFF_W2H * 2 + b_byte[np] + k2);
                ldsm_x4(w2l[np], sbase + OFF_W2L * 2 + b_byte[np] + k2);
            }

            #pragma unroll
            for (int np = 0; np < 2; np++) {
                #pragma unroll
                for (int j = 0; j < 2; j++) {
                    int nb = np * 2 + j;
                    // s path: hi*Whi + lo*Whi + hi*Wlo
                    mma_bf16(d1[nb], sh, w1h[np][j], w1h[np][j + 2]);
                    mma_bf16(d1[nb], sl, w1h[np][j], w1h[np][j + 2]);
                    mma_bf16(d1[nb], sh, w1l[np][j], w1l[np][j + 2]);
                    // p path
                    mma_bf16(d2[nb], ph, w2h[np][j], w2h[np][j + 2]);
                    mma_bf16(d2[nb], pl, w2h[np][j], w2h[np][j + 2]);
                    mma_bf16(d2[nb], ph, w2l[np][j], w2l[np][j + 2]);
                }
            }
        }
        __syncthreads();   // all warps done reading A-tiles before next prologue

        // ---- epilogue: bias + leaky_relu + sum, store fp32 ----
        int r_lo = row0 + warp_m + (lane >> 2);
        int r_hi = r_lo + 8;
        #pragma unroll
        for (int nb = 0; nb < 4; nb++) {
            int col = col_base + nb * 8;
            if (r_lo < n) {
                float2 o;
                o.x = lrelu(d1[nb][0] + b1v[nb].x) + lrelu(d2[nb][0] + b2v[nb].x);
                o.y = lrelu(d1[nb][1] + b1v[nb].y) + lrelu(d2[nb][1] + b2v[nb].y);
                *reinterpret_cast<float2*>(out + (size_t)r_lo * DIM + col) = o;
            }
            if (r_hi < n) {
                float2 o;
                o.x = lrelu(d1[nb][2] + b1v[nb].x) + lrelu(d2[nb][2] + b2v[nb].x);
                o.y = lrelu(d1[nb][3] + b1v[nb].y) + lrelu(d2[nb][3] + b2v[nb].y);
                *reinterpret_cast<float2*>(out + (size_t)r_hi * DIM + col) = o;
            }
        }
    }
}

// ---------------------------------------------------------------------------
extern "C" void kernel_launch(void* const* d_in, const int* in_sizes, int n_in,
                              void* d_out, int out_size) {
    const float* ego  = (const float*)d_in[0];
    const float* vals = (const float*)d_in[1];
    const float* W1   = (const float*)d_in[2];
    const float* b1   = (const float*)d_in[3];
    const float* W2   = (const float*)d_in[4];
    const float* b2   = (const float*)d_in[5];
    const int*   rows = (const int*)d_in[6];
    const int*   cols = (const int*)d_in[7];
    float*       out  = (float*)d_out;

    int n = in_sizes[0] / DIM;   // 50000
    int E = in_sizes[1];         // 640000

    cudaFuncSetAttribute(dense_kernel,
                         cudaFuncAttributeMaxDynamicSharedMemorySize, SMEM_BYTES);

    // 1) zero scratch (async memset: graph-capturable, no alloc)
    void* side_ptr = nullptr;
    cudaGetSymbolAddress(&side_ptr, g_side);
    cudaMemsetAsync(side_ptr, 0, (size_t)n * DIM * sizeof(float));

    // 2) edge scatter (one warp per edge, 8 warps/block)
    int blocks = (E + 7) / 8;
    scatter_kernel<<<blocks, 256>>>(ego, vals, rows, cols, E);

    // 3) fused dense (tensor cores, 16 warps)
    dense_kernel<<<148, THREADS, SMEM_BYTES>>>(ego, W1, b1, W2, b2, out, n);
}